// round 11
// baseline (speedup 1.0000x reference)
#include <cuda_runtime.h>
#include <cuda_fp16.h>
#include <cstdint>

#define S_DIM 2048
#define B_DIM 32
#define H_DIM 1024
#define M_TOTAL (S_DIM * B_DIM)   // 65536 rows of the big GEMM

// ---------------- scratch (device globals; no allocations allowed) ----------
__device__ __align__(16) __half g_keyh[(size_t)M_TOTAL * H_DIM];   // 128 MB fp16 key
__device__ __align__(16) __half g_UaT[(size_t)H_DIM * H_DIM];      // Ua^T fp16 ([n][k], k contiguous)
__device__ __align__(16) float  g_qW[B_DIM * H_DIM];               // q@Wa + Wa_b + Ua_b
__device__ __align__(16) float  g_qWpart[8 * B_DIM * H_DIM];       // split-k partials
__device__ __align__(16) float  g_partial[(size_t)16 * M_TOTAL];   // per (N-tile x warp-col) score partials
__device__ __align__(16) float  g_ctxpart[(size_t)8 * B_DIM * H_DIM];

// ---------------- small helpers ---------------------------------------------
__device__ __forceinline__ uint32_t smem_u32(const void* p) {
    uint32_t a;
    asm("{ .reg .u64 t; cvta.to.shared.u64 t, %1; cvt.u32.u64 %0, t; }" : "=r"(a) : "l"(p));
    return a;
}

__device__ __forceinline__ void cp16(uint32_t dst, const void* src) {
    asm volatile("cp.async.cg.shared.global [%0], [%1], 16;" :: "r"(dst), "l"(src));
}

__device__ __forceinline__ void ldm4(uint32_t& r0, uint32_t& r1, uint32_t& r2, uint32_t& r3,
                                     uint32_t addr) {
    asm volatile("ldmatrix.sync.aligned.m8n8.x4.shared.b16 {%0,%1,%2,%3}, [%4];"
                 : "=r"(r0), "=r"(r1), "=r"(r2), "=r"(r3) : "r"(addr));
}

__device__ __forceinline__ void mma16816(float* c, const uint32_t* a, const uint32_t* b) {
    asm volatile(
        "mma.sync.aligned.m16n8k16.row.col.f32.f16.f16.f32 "
        "{%0,%1,%2,%3}, {%4,%5,%6,%7}, {%8,%9}, {%0,%1,%2,%3};"
        : "+f"(c[0]), "+f"(c[1]), "+f"(c[2]), "+f"(c[3])
        : "r"(a[0]), "r"(a[1]), "r"(a[2]), "r"(a[3]), "r"(b[0]), "r"(b[1]));
}

__device__ __forceinline__ float tanh_a(float x) {
    float y;
    asm("tanh.approx.f32 %0, %1;" : "=f"(y) : "f"(x));
    return y;
}

// ---------------- prep kernels ----------------------------------------------
__global__ void convert_key_kernel(const float* __restrict__ key) {
    const float4* in4 = (const float4*)key;
    uint4* out4 = (uint4*)g_keyh;
    size_t n8 = (size_t)M_TOTAL * H_DIM / 8;
    for (size_t i = (size_t)blockIdx.x * blockDim.x + threadIdx.x; i < n8;
         i += (size_t)gridDim.x * blockDim.x) {
        float4 a = in4[2 * i], b = in4[2 * i + 1];
        uint4 o; __half2 h;
        h = __floats2half2_rn(a.x, a.y); o.x = *(uint32_t*)&h;
        h = __floats2half2_rn(a.z, a.w); o.y = *(uint32_t*)&h;
        h = __floats2half2_rn(b.x, b.y); o.z = *(uint32_t*)&h;
        h = __floats2half2_rn(b.z, b.w); o.w = *(uint32_t*)&h;
        out4[i] = o;
    }
}

__global__ void transpose_ua_kernel(const float* __restrict__ Ua) {
    __shared__ float tile[32][33];
    int tx = threadIdx.x, ty = threadIdx.y;          // 32 x 8
    int x = blockIdx.x * 32 + tx;                    // n (read)
    int y = blockIdx.y * 32 + ty;                    // k (read)
#pragma unroll
    for (int i = 0; i < 32; i += 8)
        tile[ty + i][tx] = Ua[(size_t)(y + i) * H_DIM + x];
    __syncthreads();
    int x2 = blockIdx.y * 32 + tx;                   // k (write)
    int y2 = blockIdx.x * 32 + ty;                   // n (write)
#pragma unroll
    for (int i = 0; i < 32; i += 8)
        g_UaT[(size_t)(y2 + i) * H_DIM + x2] = __float2half_rn(tile[tx][ty + i]);
}

// split-K qW: grid (B, 8 k-chunks), each block does 128 k-rows of Wa
__global__ void qw_part_kernel(const float* __restrict__ q, const float* __restrict__ Wa) {
    int b = blockIdx.x, kc = blockIdx.y, t = threadIdx.x;  // 256 threads
    __shared__ float qs[128];
    if (t < 128) qs[t] = q[b * H_DIM + kc * 128 + t];
    __syncthreads();
    float a0 = 0.f, a1 = 0.f, a2 = 0.f, a3 = 0.f;
#pragma unroll 4
    for (int c = 0; c < 128; c++) {
        float qc = qs[c];
        const float* row = Wa + ((size_t)(kc * 128 + c) << 10);
        a0 += qc * row[t];
        a1 += qc * row[t + 256];
        a2 += qc * row[t + 512];
        a3 += qc * row[t + 768];
    }
    float* o = g_qWpart + (((size_t)kc * 32 + b) << 10);
    o[t] = a0; o[t + 256] = a1; o[t + 512] = a2; o[t + 768] = a3;
}

__global__ void qw_reduce_kernel(const float* __restrict__ Wb, const float* __restrict__ Ub) {
    int b = blockIdx.x, h = threadIdx.x;   // 1024 threads
    float acc = Wb[h] + Ub[h];
#pragma unroll
    for (int kc = 0; kc < 8; kc++)
        acc += g_qWpart[(((size_t)kc * 32 + b) << 10) + h];
    g_qW[b * H_DIM + h] = acc;
}

// ---------------- fused GEMM (mma.sync HMMA) + tanh + va-dot -----------------
// CTA tile 128(M) x 128(N), K chunks of 64, 3-stage cp.async pipeline.
// 4 warps in 2(M) x 2(N); warp tile 64 x 64 (128 fp32 accumulators).
#define ROWB 144                       // smem bytes per 64-half row (128 + 16 pad)
#define TILE_BYTES (128 * ROWB)        // 18432 per operand tile
#define STAGE (2 * TILE_BYTES)         // 36864 (A tile + B tile)
#define GEMM_SMEM (3 * STAGE)          // 110592 -> 2 CTAs/SM (smem-capped)

__global__ __launch_bounds__(128) void gemm_score_kernel(const float* __restrict__ va_w) {
    extern __shared__ char sm[];
    uint32_t sbase = smem_u32(sm);

    const int t = threadIdx.x;
    const int wid = t >> 5, lid = t & 31;
    const int nt = blockIdx.x;            // N-fastest for L2 reuse of A
    const int n0 = nt * 128;
    const int m0 = blockIdx.y * 128;
    const int wm = wid >> 1;              // 0..1 (M 64-block)
    const int wn = wid & 1;               // 0..1 (N 64-block)

    auto load_stage = [&](int s, int buf) {
        uint32_t dA = sbase + (uint32_t)buf * STAGE;
#pragma unroll
        for (int i = 0; i < 8; i++) {
            int chunk = t + i * 128;            // 1024 chunks of 16B per operand
            int row = chunk >> 3, c = chunk & 7;
            uint32_t d = dA + (uint32_t)row * ROWB + (uint32_t)c * 16;
            cp16(d,              g_keyh + ((size_t)(m0 + row) << 10) + s * 64 + c * 8);
            cp16(d + TILE_BYTES, g_UaT  + ((size_t)(n0 + row) << 10) + s * 64 + c * 8);
        }
    };

    float acc[4][8][4];
#pragma unroll
    for (int i = 0; i < 4; i++)
#pragma unroll
        for (int j = 0; j < 8; j++)
#pragma unroll
            for (int k = 0; k < 4; k++) acc[i][j][k] = 0.0f;

    load_stage(0, 0);
    asm volatile("cp.async.commit_group;" ::: "memory");
    load_stage(1, 1);
    asm volatile("cp.async.commit_group;" ::: "memory");

    const int lrow = lid & 15;
    const int lkA  = (lid >> 4) << 3;               // A: k half-offset 0/8
    const int nlB  = (lid & 7) + ((lid >> 4) << 3); // B: n row within 16-group
    const int lkB  = ((lid >> 3) & 1) << 3;         // B: k half-offset 0/8

    for (int s = 0; s < 16; s++) {
        if (s < 15) {
            asm volatile("cp.async.wait_group 1;" ::: "memory");
        } else {
            asm volatile("cp.async.wait_group 0;" ::: "memory");
        }
        __syncthreads();   // stage s visible; all warps done computing s-1

        if (s + 2 < 16) {  // prefetch s+2 into the buffer stage s-1 just vacated
            load_stage(s + 2, (s + 2) % 3);
            asm volatile("cp.async.commit_group;" ::: "memory");
        }

        uint32_t sA = sbase + (uint32_t)(s % 3) * STAGE;
        uint32_t sB = sA + TILE_BYTES;
#pragma unroll
        for (int ks = 0; ks < 4; ks++) {
            uint32_t a[4][4], b[4][4];
#pragma unroll
            for (int mi = 0; mi < 4; mi++) {
                uint32_t addr = sA + (uint32_t)(wm * 64 + mi * 16 + lrow) * ROWB
                                   + (uint32_t)(ks * 32 + lkA * 2);
                ldm4(a[mi][0], a[mi][1], a[mi][2], a[mi][3], addr);
            }
#pragma unroll
            for (int g = 0; g < 4; g++) {
                uint32_t addr = sB + (uint32_t)(wn * 64 + g * 16 + nlB) * ROWB
                                   + (uint32_t)(ks * 32 + lkB * 2);
                ldm4(b[g][0], b[g][1], b[g][2], b[g][3], addr);
            }
#pragma unroll
            for (int mi = 0; mi < 4; mi++) {
#pragma unroll
                for (int g = 0; g < 4; g++) {
                    mma16816(acc[mi][g * 2],     a[mi], &b[g][0]);
                    mma16816(acc[mi][g * 2 + 1], a[mi], &b[g][2]);
                }
            }
        }
    }

    // ---- epilogue: tanh + va-dot; qW/va straight from L2 ----------------------
#pragma unroll
    for (int mi = 0; mi < 4; mi++) {
        float sumA = 0.f, sumB = 0.f;
        int rloc = wm * 64 + mi * 16 + (lid >> 2);
        int bA = rloc & 31;             // m0 is a multiple of 128
        int bB = (rloc + 8) & 31;
        const float* qa = g_qW + bA * H_DIM + n0;
        const float* qb = g_qW + bB * H_DIM + n0;
#pragma unroll
        for (int j = 0; j < 8; j++) {
            int nl = wn * 64 + j * 8 + 2 * (lid & 3);
            float2 va2 = *(const float2*)(va_w + n0 + nl);
            float2 qa2 = *(const float2*)(qa + nl);
            float2 qb2 = *(const float2*)(qb + nl);
            sumA += va2.x * tanh_a(acc[mi][j][0] + qa2.x)
                  + va2.y * tanh_a(acc[mi][j][1] + qa2.y);
            sumB += va2.x * tanh_a(acc[mi][j][2] + qb2.x)
                  + va2.y * tanh_a(acc[mi][j][3] + qb2.y);
        }
        sumA += __shfl_xor_sync(0xFFFFFFFFu, sumA, 1);
        sumA += __shfl_xor_sync(0xFFFFFFFFu, sumA, 2);
        sumB += __shfl_xor_sync(0xFFFFFFFFu, sumB, 1);
        sumB += __shfl_xor_sync(0xFFFFFFFFu, sumB, 2);
        if ((lid & 3) == 0) {
            int r = m0 + rloc;
            size_t slot = (size_t)(nt * 2 + wn) * M_TOTAL;
            g_partial[slot + r]     = sumA;
            g_partial[slot + r + 8] = sumB;
        }
    }
}

// ---------------- softmax + context ------------------------------------------
__global__ void softmax_kernel(float* __restrict__ out) {
    int b = blockIdx.x, t = threadIdx.x;   // 256 threads
    __shared__ float sc[S_DIM];
    __shared__ float red[256];
    float lmax = -1e30f;
#pragma unroll
    for (int j = 0; j < 8; j++) {
        int s = t + j * 256;
        size_t r = (size_t)s * 32 + b;
        float v = 0.0f;
#pragma unroll
        for (int p = 0; p < 16; p++) v += g_partial[(size_t)p * M_TOTAL + r];
        sc[s] = v;
        lmax = fmaxf(lmax, v);
    }
    red[t] = lmax; __syncthreads();
    for (int o = 128; o > 0; o >>= 1) {
        if (t < o) red[t] = fmaxf(red[t], red[t + o]);
        __syncthreads();
    }
    float mx = red[0];
    __syncthreads();
    float lsum = 0.0f;
#pragma unroll
    for (int j = 0; j < 8; j++) {
        int s = t + j * 256;
        float e = __expf(sc[s] - mx);
        sc[s] = e;
        lsum += e;
    }
    red[t] = lsum; __syncthreads();
    for (int o = 128; o > 0; o >>= 1) {
        if (t < o) red[t] += red[t + o];
        __syncthreads();
    }
    float inv = 1.0f / red[0];
#pragma unroll
    for (int j = 0; j < 8; j++) {
        int s = t + j * 256;
        out[B_DIM * H_DIM + b * S_DIM + s] = sc[s] * inv;
    }
}

__global__ void context_part_kernel(const float* __restrict__ out) {
    int b = blockIdx.x, chunk = blockIdx.y, t = threadIdx.x;   // 256 threads
    __shared__ float w_s[256];
    w_s[t] = out[B_DIM * H_DIM + b * S_DIM + chunk * 256 + t];
    __syncthreads();
    int h0 = t * 4;
    float a0 = 0.f, a1 = 0.f, a2 = 0.f, a3 = 0.f;
#pragma unroll 4
    for (int si = 0; si < 256; si++) {
        int s = chunk * 256 + si;
        const __half* kp = g_keyh + (((size_t)s * 32 + b) << 10) + h0;
        uint2 raw = *(const uint2*)kp;
        __half2 p0 = *(__half2*)&raw.x, p1 = *(__half2*)&raw.y;
        float w = w_s[si];
        float2 f0 = __half22float2(p0), f1 = __half22float2(p1);
        a0 += w * f0.x; a1 += w * f0.y; a2 += w * f1.x; a3 += w * f1.y;
    }
    float* cp = g_ctxpart + (((size_t)chunk * 32 + b) << 10) + h0;
    cp[0] = a0; cp[1] = a1; cp[2] = a2; cp[3] = a3;
}

__global__ void context_reduce_kernel(float* __restrict__ out) {
    int b = blockIdx.x, h = threadIdx.x;   // 1024 threads
    float acc = 0.0f;
#pragma unroll
    for (int c = 0; c < 8; c++)
        acc += g_ctxpart[(((size_t)c * 32 + b) << 10) + h];
    out[b * H_DIM + h] = acc;
}

// ---------------- launch ------------------------------------------------------
extern "C" void kernel_launch(void* const* d_in, const int* in_sizes, int n_in,
                              void* d_out, int out_size) {
    const float* query = (const float*)d_in[0];
    const float* key   = (const float*)d_in[1];
    const float* Wa_w  = (const float*)d_in[2];
    const float* Wa_b  = (const float*)d_in[3];
    const float* Ua_w  = (const float*)d_in[4];
    const float* Ua_b  = (const float*)d_in[5];
    const float* va_w  = (const float*)d_in[6];
    // d_in[7] (va_b) is a uniform score shift -> softmax-invariant -> unused
    float* out = (float*)d_out;

    cudaFuncSetAttribute(gemm_score_kernel,
                         cudaFuncAttributeMaxDynamicSharedMemorySize, GEMM_SMEM);

    convert_key_kernel<<<4096, 256>>>(key);
    transpose_ua_kernel<<<dim3(32, 32), dim3(32, 8)>>>(Ua_w);
    qw_part_kernel<<<dim3(B_DIM, 8), 256>>>(query, Wa_w);
    qw_reduce_kernel<<<B_DIM, 1024>>>(Wa_b, Ua_b);
    gemm_score_kernel<<<dim3(8, 512), 128, GEMM_SMEM>>>(va_w);
    softmax_kernel<<<B_DIM, 256>>>(out);
    context_part_kernel<<<dim3(B_DIM, 8), 256>>>(out);
    context_reduce_kernel<<<B_DIM, 1024>>>(out);
}

// round 12
// speedup vs baseline: 1.0740x; 1.0740x over previous
#include <cuda_runtime.h>
#include <cuda_fp16.h>
#include <cstdint>

#define S_DIM 2048
#define B_DIM 32
#define H_DIM 1024
#define M_TOTAL (S_DIM * B_DIM)   // 65536 rows of the big GEMM

// ---------------- scratch (device globals; no allocations allowed) ----------
__device__ __align__(16) __half g_keyh[(size_t)M_TOTAL * H_DIM];   // 128 MB fp16 key
__device__ __align__(16) __half g_UaT[(size_t)H_DIM * H_DIM];      // Ua^T fp16 ([n][k], k contiguous)
__device__ __align__(16) float  g_qW[B_DIM * H_DIM];               // q@Wa + Wa_b + Ua_b
__device__ __align__(16) float  g_qWpart[8 * B_DIM * H_DIM];       // split-k partials
__device__ __align__(16) float  g_partial[(size_t)32 * M_TOTAL];   // per (N-tile x warp-col) score partials
__device__ __align__(16) float  g_ctxpart[(size_t)8 * B_DIM * H_DIM];

// ---------------- small helpers ---------------------------------------------
__device__ __forceinline__ uint32_t smem_u32(const void* p) {
    uint32_t a;
    asm("{ .reg .u64 t; cvta.to.shared.u64 t, %1; cvt.u32.u64 %0, t; }" : "=r"(a) : "l"(p));
    return a;
}

__device__ __forceinline__ void cp16(uint32_t dst, const void* src) {
    asm volatile("cp.async.cg.shared.global [%0], [%1], 16;" :: "r"(dst), "l"(src));
}

__device__ __forceinline__ void ldm4(uint32_t& r0, uint32_t& r1, uint32_t& r2, uint32_t& r3,
                                     uint32_t addr) {
    asm volatile("ldmatrix.sync.aligned.m8n8.x4.shared.b16 {%0,%1,%2,%3}, [%4];"
                 : "=r"(r0), "=r"(r1), "=r"(r2), "=r"(r3) : "r"(addr));
}

__device__ __forceinline__ void mma16816(float* c, const uint32_t* a, const uint32_t* b) {
    asm volatile(
        "mma.sync.aligned.m16n8k16.row.col.f32.f16.f16.f32 "
        "{%0,%1,%2,%3}, {%4,%5,%6,%7}, {%8,%9}, {%0,%1,%2,%3};"
        : "+f"(c[0]), "+f"(c[1]), "+f"(c[2]), "+f"(c[3])
        : "r"(a[0]), "r"(a[1]), "r"(a[2]), "r"(a[3]), "r"(b[0]), "r"(b[1]));
}

__device__ __forceinline__ float tanh_a(float x) {
    float y;
    asm("tanh.approx.f32 %0, %1;" : "=f"(y) : "f"(x));
    return y;
}

// ---------------- fused prep kernel ------------------------------------------
// One grid, three independent jobs partitioned by blockIdx.x:
//   [0, 256)        qw_part   (32 b x 8 k-chunks)
//   [256, 1280)     transpose (32 x 32 tiles of Ua)
//   [1280, 5376)    key fp32->fp16 convert (bandwidth-bound; hides the others)
#define PREP_QW_BLKS   256
#define PREP_TR_BLKS   1024
#define PREP_CV_BLKS   4096
#define PREP_BLKS      (PREP_QW_BLKS + PREP_TR_BLKS + PREP_CV_BLKS)

__global__ __launch_bounds__(256) void prep_kernel(
    const float* __restrict__ key, const float* __restrict__ Ua,
    const float* __restrict__ q,   const float* __restrict__ Wa) {
    __shared__ float smem[32 * 33];          // max of: transpose tile (4224B), qs (512B)
    const int bid = blockIdx.x;
    const int t = threadIdx.x;

    if (bid < PREP_QW_BLKS) {
        // ---- split-K qW partials: 128 k-rows of Wa per block -----------------
        int b = bid & 31, kc = bid >> 5;
        float* qs = smem;
        if (t < 128) qs[t] = q[b * H_DIM + kc * 128 + t];
        __syncthreads();
        float a0 = 0.f, a1 = 0.f, a2 = 0.f, a3 = 0.f;
#pragma unroll 4
        for (int c = 0; c < 128; c++) {
            float qc = qs[c];
            const float* row = Wa + ((size_t)(kc * 128 + c) << 10);
            a0 += qc * row[t];
            a1 += qc * row[t + 256];
            a2 += qc * row[t + 512];
            a3 += qc * row[t + 768];
        }
        float* o = g_qWpart + (((size_t)kc * 32 + b) << 10);
        o[t] = a0; o[t + 256] = a1; o[t + 512] = a2; o[t + 768] = a3;
    } else if (bid < PREP_QW_BLKS + PREP_TR_BLKS) {
        // ---- Ua transpose -> fp16 g_UaT --------------------------------------
        int b2 = bid - PREP_QW_BLKS;
        int bx = b2 & 31, by = b2 >> 5;
        int tx = t & 31, ty = t >> 5;        // 32 x 8
        float (*tile)[33] = (float (*)[33])smem;
        int x = bx * 32 + tx;                // n (read)
        int y = by * 32 + ty;                // k (read)
#pragma unroll
        for (int i = 0; i < 32; i += 8)
            tile[ty + i][tx] = Ua[(size_t)(y + i) * H_DIM + x];
        __syncthreads();
        int x2 = by * 32 + tx;               // k (write)
        int y2 = bx * 32 + ty;               // n (write)
#pragma unroll
        for (int i = 0; i < 32; i += 8)
            g_UaT[(size_t)(y2 + i) * H_DIM + x2] = __float2half_rn(tile[tx][ty + i]);
    } else {
        // ---- key fp32 -> fp16 convert ----------------------------------------
        int b3 = bid - PREP_QW_BLKS - PREP_TR_BLKS;
        const float4* in4 = (const float4*)key;
        uint4* out4 = (uint4*)g_keyh;
        size_t n8 = (size_t)M_TOTAL * H_DIM / 8;
        for (size_t i = (size_t)b3 * 256 + t; i < n8; i += (size_t)PREP_CV_BLKS * 256) {
            float4 a = in4[2 * i], b = in4[2 * i + 1];
            uint4 o; __half2 h;
            h = __floats2half2_rn(a.x, a.y); o.x = *(uint32_t*)&h;
            h = __floats2half2_rn(a.z, a.w); o.y = *(uint32_t*)&h;
            h = __floats2half2_rn(b.x, b.y); o.z = *(uint32_t*)&h;
            h = __floats2half2_rn(b.z, b.w); o.w = *(uint32_t*)&h;
            out4[i] = o;
        }
    }
}

__global__ void qw_reduce_kernel(const float* __restrict__ Wb, const float* __restrict__ Ub) {
    int b = blockIdx.x, h = threadIdx.x;   // 1024 threads
    float acc = Wb[h] + Ub[h];
#pragma unroll
    for (int kc = 0; kc < 8; kc++)
        acc += g_qWpart[(((size_t)kc * 32 + b) << 10) + h];
    g_qW[b * H_DIM + h] = acc;
}

// ---------------- fused GEMM (mma.sync HMMA) + tanh + va-dot -----------------
// CTA tile 128(M) x 128(N), K chunks of 64, 3-stage cp.async pipeline,
// one __syncthreads per stage. 8 warps in 2(M) x 4(N); warp tile 64 x 32.
#define ROWB 144                       // smem bytes per 64-half row (128 + 16 pad)
#define TILE_BYTES (128 * ROWB)        // 18432 per operand tile
#define STAGE (2 * TILE_BYTES)         // 36864 (A tile + B tile)
#define GEMM_SMEM (3 * STAGE)          // 110592 -> 2 CTAs/SM

__global__ __launch_bounds__(256, 2) void gemm_score_kernel(const float* __restrict__ va_w) {
    extern __shared__ char sm[];
    uint32_t sbase = smem_u32(sm);

    const int t = threadIdx.x;
    const int wid = t >> 5, lid = t & 31;
    const int nt = blockIdx.x;            // N-fastest for L2 reuse of A
    const int n0 = nt * 128;
    const int m0 = blockIdx.y * 128;
    const int wm = wid >> 2;              // 0..1
    const int wn = wid & 3;               // 0..3

    auto load_stage = [&](int s, int buf) {
        uint32_t dA = sbase + (uint32_t)buf * STAGE;
#pragma unroll
        for (int i = 0; i < 4; i++) {
            int chunk = t + i * 256;            // 1024 chunks of 16B per operand
            int row = chunk >> 3, c = chunk & 7;
            uint32_t d = dA + (uint32_t)row * ROWB + (uint32_t)c * 16;
            cp16(d,              g_keyh + ((size_t)(m0 + row) << 10) + s * 64 + c * 8);
            cp16(d + TILE_BYTES, g_UaT  + ((size_t)(n0 + row) << 10) + s * 64 + c * 8);
        }
    };

    float acc[4][4][4];
#pragma unroll
    for (int i = 0; i < 4; i++)
#pragma unroll
        for (int j = 0; j < 4; j++)
#pragma unroll
            for (int k = 0; k < 4; k++) acc[i][j][k] = 0.0f;

    load_stage(0, 0);
    asm volatile("cp.async.commit_group;" ::: "memory");
    load_stage(1, 1);
    asm volatile("cp.async.commit_group;" ::: "memory");

    const int lrow = lid & 15;
    const int lkA  = (lid >> 4) << 3;               // A: k half-offset 0/8
    const int nlB  = (lid & 7) + ((lid >> 4) << 3); // B: n row within 16-group
    const int lkB  = ((lid >> 3) & 1) << 3;         // B: k half-offset 0/8

    for (int s = 0; s < 16; s++) {
        if (s < 15) {
            asm volatile("cp.async.wait_group 1;" ::: "memory");
        } else {
            asm volatile("cp.async.wait_group 0;" ::: "memory");
        }
        __syncthreads();   // stage s visible; all warps done computing s-1

        if (s + 2 < 16) {  // prefetch s+2 into the buffer stage s-1 just vacated
            load_stage(s + 2, (s + 2) % 3);
            asm volatile("cp.async.commit_group;" ::: "memory");
        }

        uint32_t sA = sbase + (uint32_t)(s % 3) * STAGE;
        uint32_t sB = sA + TILE_BYTES;
#pragma unroll
        for (int ks = 0; ks < 4; ks++) {
            uint32_t a[4][4], b[2][4];
#pragma unroll
            for (int mi = 0; mi < 4; mi++) {
                uint32_t addr = sA + (uint32_t)(wm * 64 + mi * 16 + lrow) * ROWB
                                   + (uint32_t)(ks * 32 + lkA * 2);
                ldm4(a[mi][0], a[mi][1], a[mi][2], a[mi][3], addr);
            }
#pragma unroll
            for (int g = 0; g < 2; g++) {
                uint32_t addr = sB + (uint32_t)(wn * 32 + g * 16 + nlB) * ROWB
                                   + (uint32_t)(ks * 32 + lkB * 2);
                ldm4(b[g][0], b[g][1], b[g][2], b[g][3], addr);
            }
#pragma unroll
            for (int mi = 0; mi < 4; mi++) {
#pragma unroll
                for (int g = 0; g < 2; g++) {
                    mma16816(acc[mi][g * 2],     a[mi], &b[g][0]);
                    mma16816(acc[mi][g * 2 + 1], a[mi], &b[g][2]);
                }
            }
        }
    }

    // ---- epilogue: tanh + va-dot; qW/va straight from L2 ----------------------
#pragma unroll
    for (int mi = 0; mi < 4; mi++) {
        float sumA = 0.f, sumB = 0.f;
        int rloc = wm * 64 + mi * 16 + (lid >> 2);
        int bA = rloc & 31;             // m0 is a multiple of 128
        int bB = (rloc + 8) & 31;
        const float* qa = g_qW + bA * H_DIM + n0;
        const float* qb = g_qW + bB * H_DIM + n0;
#pragma unroll
        for (int j = 0; j < 4; j++) {
            int nl = wn * 32 + j * 8 + 2 * (lid & 3);
            float2 va2 = *(const float2*)(va_w + n0 + nl);
            float2 qa2 = *(const float2*)(qa + nl);
            float2 qb2 = *(const float2*)(qb + nl);
            sumA += va2.x * tanh_a(acc[mi][j][0] + qa2.x)
                  + va2.y * tanh_a(acc[mi][j][1] + qa2.y);
            sumB += va2.x * tanh_a(acc[mi][j][2] + qb2.x)
                  + va2.y * tanh_a(acc[mi][j][3] + qb2.y);
        }
        sumA += __shfl_xor_sync(0xFFFFFFFFu, sumA, 1);
        sumA += __shfl_xor_sync(0xFFFFFFFFu, sumA, 2);
        sumB += __shfl_xor_sync(0xFFFFFFFFu, sumB, 1);
        sumB += __shfl_xor_sync(0xFFFFFFFFu, sumB, 2);
        if ((lid & 3) == 0) {
            int r = m0 + rloc;
            size_t slot = (size_t)(nt * 4 + wn) * M_TOTAL;
            g_partial[slot + r]     = sumA;
            g_partial[slot + r + 8] = sumB;
        }
    }
}

// ---------------- softmax + context ------------------------------------------
__global__ void softmax_kernel(float* __restrict__ out) {
    int b = blockIdx.x, t = threadIdx.x;   // 256 threads
    __shared__ float sc[S_DIM];
    __shared__ float red[256];
    float lmax = -1e30f;
#pragma unroll
    for (int j = 0; j < 8; j++) {
        int s = t + j * 256;
        size_t r = (size_t)s * 32 + b;
        float v = 0.0f;
#pragma unroll
        for (int p = 0; p < 32; p++) v += g_partial[(size_t)p * M_TOTAL + r];
        sc[s] = v;
        lmax = fmaxf(lmax, v);
    }
    red[t] = lmax; __syncthreads();
    for (int o = 128; o > 0; o >>= 1) {
        if (t < o) red[t] = fmaxf(red[t], red[t + o]);
        __syncthreads();
    }
    float mx = red[0];
    __syncthreads();
    float lsum = 0.0f;
#pragma unroll
    for (int j = 0; j < 8; j++) {
        int s = t + j * 256;
        float e = __expf(sc[s] - mx);
        sc[s] = e;
        lsum += e;
    }
    red[t] = lsum; __syncthreads();
    for (int o = 128; o > 0; o >>= 1) {
        if (t < o) red[t] += red[t + o];
        __syncthreads();
    }
    float inv = 1.0f / red[0];
#pragma unroll
    for (int j = 0; j < 8; j++) {
        int s = t + j * 256;
        out[B_DIM * H_DIM + b * S_DIM + s] = sc[s] * inv;
    }
}

__global__ void context_part_kernel(const float* __restrict__ out) {
    int b = blockIdx.x, chunk = blockIdx.y, t = threadIdx.x;   // 256 threads
    __shared__ float w_s[256];
    w_s[t] = out[B_DIM * H_DIM + b * S_DIM + chunk * 256 + t];
    __syncthreads();
    int h0 = t * 4;
    float a0 = 0.f, a1 = 0.f, a2 = 0.f, a3 = 0.f;
#pragma unroll 4
    for (int si = 0; si < 256; si++) {
        int s = chunk * 256 + si;
        const __half* kp = g_keyh + (((size_t)s * 32 + b) << 10) + h0;
        uint2 raw = *(const uint2*)kp;
        __half2 p0 = *(__half2*)&raw.x, p1 = *(__half2*)&raw.y;
        float w = w_s[si];
        float2 f0 = __half22float2(p0), f1 = __half22float2(p1);
        a0 += w * f0.x; a1 += w * f0.y; a2 += w * f1.x; a3 += w * f1.y;
    }
    float* cp = g_ctxpart + (((size_t)chunk * 32 + b) << 10) + h0;
    cp[0] = a0; cp[1] = a1; cp[2] = a2; cp[3] = a3;
}

__global__ void context_reduce_kernel(float* __restrict__ out) {
    int b = blockIdx.x, h = threadIdx.x;   // 1024 threads
    float acc = 0.0f;
#pragma unroll
    for (int c = 0; c < 8; c++)
        acc += g_ctxpart[(((size_t)c * 32 + b) << 10) + h];
    out[b * H_DIM + h] = acc;
}

// ---------------- launch ------------------------------------------------------
extern "C" void kernel_launch(void* const* d_in, const int* in_sizes, int n_in,
                              void* d_out, int out_size) {
    const float* query = (const float*)d_in[0];
    const float* key   = (const float*)d_in[1];
    const float* Wa_w  = (const float*)d_in[2];
    const float* Wa_b  = (const float*)d_in[3];
    const float* Ua_w  = (const float*)d_in[4];
    const float* Ua_b  = (const float*)d_in[5];
    const float* va_w  = (const float*)d_in[6];
    // d_in[7] (va_b) is a uniform score shift -> softmax-invariant -> unused
    float* out = (float*)d_out;

    cudaFuncSetAttribute(gemm_score_kernel,
                         cudaFuncAttributeMaxDynamicSharedMemorySize, GEMM_SMEM);

    prep_kernel<<<PREP_BLKS, 256>>>(key, Ua_w, query, Wa_w);
    qw_reduce_kernel<<<B_DIM, 1024>>>(Wa_b, Ua_b);
    gemm_score_kernel<<<dim3(8, 512), 256, GEMM_SMEM>>>(va_w);
    softmax_kernel<<<B_DIM, 256>>>(out);
    context_part_kernel<<<dim3(B_DIM, 8), 256>>>(out);
    context_reduce_kernel<<<B_DIM, 1024>>>(out);
}

// round 13
// speedup vs baseline: 1.1463x; 1.0674x over previous
#include <cuda_runtime.h>
#include <cuda_fp16.h>
#include <cstdint>

#define S_DIM 2048
#define B_DIM 32
#define H_DIM 1024
#define M_TOTAL (S_DIM * B_DIM)   // 65536 rows of the big GEMM

// ---------------- scratch (device globals; no allocations allowed) ----------
__device__ __align__(16) __half g_keyh[(size_t)M_TOTAL * H_DIM];   // 128 MB fp16 key
__device__ __align__(16) __half g_UaT[(size_t)H_DIM * H_DIM];      // Ua^T fp16 ([n][k], k contiguous)
__device__ __align__(16) float  g_qW[B_DIM * H_DIM];               // q@Wa + Wa_b + Ua_b
__device__ __align__(16) float  g_qWpart[8 * B_DIM * H_DIM];       // split-k partials
__device__ __align__(16) float  g_partial[(size_t)32 * M_TOTAL];   // per (N-tile x warp-col) score partials
__device__ __align__(16) float  g_scores[B_DIM * S_DIM];           // reduced scores, b-major
__device__ __align__(16) float  g_ctxpart[(size_t)8 * B_DIM * H_DIM];

// ---------------- small helpers ---------------------------------------------
__device__ __forceinline__ uint32_t smem_u32(const void* p) {
    uint32_t a;
    asm("{ .reg .u64 t; cvta.to.shared.u64 t, %1; cvt.u32.u64 %0, t; }" : "=r"(a) : "l"(p));
    return a;
}

__device__ __forceinline__ void cp16(uint32_t dst, const void* src) {
    asm volatile("cp.async.cg.shared.global [%0], [%1], 16;" :: "r"(dst), "l"(src));
}

__device__ __forceinline__ void ldm4(uint32_t& r0, uint32_t& r1, uint32_t& r2, uint32_t& r3,
                                     uint32_t addr) {
    asm volatile("ldmatrix.sync.aligned.m8n8.x4.shared.b16 {%0,%1,%2,%3}, [%4];"
                 : "=r"(r0), "=r"(r1), "=r"(r2), "=r"(r3) : "r"(addr));
}

__device__ __forceinline__ void mma16816(float* c, const uint32_t* a, const uint32_t* b) {
    asm volatile(
        "mma.sync.aligned.m16n8k16.row.col.f32.f16.f16.f32 "
        "{%0,%1,%2,%3}, {%4,%5,%6,%7}, {%8,%9}, {%0,%1,%2,%3};"
        : "+f"(c[0]), "+f"(c[1]), "+f"(c[2]), "+f"(c[3])
        : "r"(a[0]), "r"(a[1]), "r"(a[2]), "r"(a[3]), "r"(b[0]), "r"(b[1]));
}

__device__ __forceinline__ float tanh_a(float x) {
    float y;
    asm("tanh.approx.f32 %0, %1;" : "=f"(y) : "f"(x));
    return y;
}

// ---------------- fused prep kernel ------------------------------------------
// One grid, three independent jobs partitioned by blockIdx.x:
//   [0, 256)        qw_part   (32 b x 8 k-chunks)
//   [256, 1280)     transpose (32 x 32 tiles of Ua)
//   [1280, 5376)    key fp32->fp16 convert (bandwidth-bound; hides the others)
#define PREP_QW_BLKS   256
#define PREP_TR_BLKS   1024
#define PREP_CV_BLKS   4096
#define PREP_BLKS      (PREP_QW_BLKS + PREP_TR_BLKS + PREP_CV_BLKS)

__global__ __launch_bounds__(256) void prep_kernel(
    const float* __restrict__ key, const float* __restrict__ Ua,
    const float* __restrict__ q,   const float* __restrict__ Wa) {
    __shared__ float smem[32 * 33];          // max of: transpose tile (4224B), qs (512B)
    const int bid = blockIdx.x;
    const int t = threadIdx.x;

    if (bid < PREP_QW_BLKS) {
        // ---- split-K qW partials: 128 k-rows of Wa per block -----------------
        int b = bid & 31, kc = bid >> 5;
        float* qs = smem;
        if (t < 128) qs[t] = q[b * H_DIM + kc * 128 + t];
        __syncthreads();
        float a0 = 0.f, a1 = 0.f, a2 = 0.f, a3 = 0.f;
#pragma unroll 4
        for (int c = 0; c < 128; c++) {
            float qc = qs[c];
            const float* row = Wa + ((size_t)(kc * 128 + c) << 10);
            a0 += qc * row[t];
            a1 += qc * row[t + 256];
            a2 += qc * row[t + 512];
            a3 += qc * row[t + 768];
        }
        float* o = g_qWpart + (((size_t)kc * 32 + b) << 10);
        o[t] = a0; o[t + 256] = a1; o[t + 512] = a2; o[t + 768] = a3;
    } else if (bid < PREP_QW_BLKS + PREP_TR_BLKS) {
        // ---- Ua transpose -> fp16 g_UaT --------------------------------------
        int b2 = bid - PREP_QW_BLKS;
        int bx = b2 & 31, by = b2 >> 5;
        int tx = t & 31, ty = t >> 5;        // 32 x 8
        float (*tile)[33] = (float (*)[33])smem;
        int x = bx * 32 + tx;                // n (read)
        int y = by * 32 + ty;                // k (read)
#pragma unroll
        for (int i = 0; i < 32; i += 8)
            tile[ty + i][tx] = Ua[(size_t)(y + i) * H_DIM + x];
        __syncthreads();
        int x2 = by * 32 + tx;               // k (write)
        int y2 = bx * 32 + ty;               // n (write)
#pragma unroll
        for (int i = 0; i < 32; i += 8)
            g_UaT[(size_t)(y2 + i) * H_DIM + x2] = __float2half_rn(tile[tx][ty + i]);
    } else {
        // ---- key fp32 -> fp16 convert ----------------------------------------
        int b3 = bid - PREP_QW_BLKS - PREP_TR_BLKS;
        const float4* in4 = (const float4*)key;
        uint4* out4 = (uint4*)g_keyh;
        size_t n8 = (size_t)M_TOTAL * H_DIM / 8;
        for (size_t i = (size_t)b3 * 256 + t; i < n8; i += (size_t)PREP_CV_BLKS * 256) {
            float4 a = in4[2 * i], b = in4[2 * i + 1];
            uint4 o; __half2 h;
            h = __floats2half2_rn(a.x, a.y); o.x = *(uint32_t*)&h;
            h = __floats2half2_rn(a.z, a.w); o.y = *(uint32_t*)&h;
            h = __floats2half2_rn(b.x, b.y); o.z = *(uint32_t*)&h;
            h = __floats2half2_rn(b.z, b.w); o.w = *(uint32_t*)&h;
            out4[i] = o;
        }
    }
}

__global__ void qw_reduce_kernel(const float* __restrict__ Wb, const float* __restrict__ Ub) {
    int b = blockIdx.x, h = threadIdx.x;   // 1024 threads
    float acc = Wb[h] + Ub[h];
#pragma unroll
    for (int kc = 0; kc < 8; kc++)
        acc += g_qWpart[(((size_t)kc * 32 + b) << 10) + h];
    g_qW[b * H_DIM + h] = acc;
}

// ---------------- fused GEMM (mma.sync HMMA) + tanh + va-dot -----------------
// CTA tile 128(M) x 128(N), K chunks of 64, 3-stage cp.async pipeline,
// one __syncthreads per stage. 8 warps in 2(M) x 4(N); warp tile 64 x 32.
#define ROWB 144                       // smem bytes per 64-half row (128 + 16 pad)
#define TILE_BYTES (128 * ROWB)        // 18432 per operand tile
#define STAGE (2 * TILE_BYTES)         // 36864 (A tile + B tile)
#define GEMM_SMEM (3 * STAGE)          // 110592 -> 2 CTAs/SM

__global__ __launch_bounds__(256, 2) void gemm_score_kernel(const float* __restrict__ va_w) {
    extern __shared__ char sm[];
    uint32_t sbase = smem_u32(sm);

    const int t = threadIdx.x;
    const int wid = t >> 5, lid = t & 31;
    const int nt = blockIdx.x;            // N-fastest for L2 reuse of A
    const int n0 = nt * 128;
    const int m0 = blockIdx.y * 128;
    const int wm = wid >> 2;              // 0..1
    const int wn = wid & 3;               // 0..3

    auto load_stage = [&](int s, int buf) {
        uint32_t dA = sbase + (uint32_t)buf * STAGE;
#pragma unroll
        for (int i = 0; i < 4; i++) {
            int chunk = t + i * 256;            // 1024 chunks of 16B per operand
            int row = chunk >> 3, c = chunk & 7;
            uint32_t d = dA + (uint32_t)row * ROWB + (uint32_t)c * 16;
            cp16(d,              g_keyh + ((size_t)(m0 + row) << 10) + s * 64 + c * 8);
            cp16(d + TILE_BYTES, g_UaT  + ((size_t)(n0 + row) << 10) + s * 64 + c * 8);
        }
    };

    float acc[4][4][4];
#pragma unroll
    for (int i = 0; i < 4; i++)
#pragma unroll
        for (int j = 0; j < 4; j++)
#pragma unroll
            for (int k = 0; k < 4; k++) acc[i][j][k] = 0.0f;

    load_stage(0, 0);
    asm volatile("cp.async.commit_group;" ::: "memory");
    load_stage(1, 1);
    asm volatile("cp.async.commit_group;" ::: "memory");

    const int lrow = lid & 15;
    const int lkA  = (lid >> 4) << 3;               // A: k half-offset 0/8
    const int nlB  = (lid & 7) + ((lid >> 4) << 3); // B: n row within 16-group
    const int lkB  = ((lid >> 3) & 1) << 3;         // B: k half-offset 0/8

    for (int s = 0; s < 16; s++) {
        if (s < 15) {
            asm volatile("cp.async.wait_group 1;" ::: "memory");
        } else {
            asm volatile("cp.async.wait_group 0;" ::: "memory");
        }
        __syncthreads();   // stage s visible; all warps done computing s-1

        if (s + 2 < 16) {  // prefetch s+2 into the buffer stage s-1 just vacated
            load_stage(s + 2, (s + 2) % 3);
            asm volatile("cp.async.commit_group;" ::: "memory");
        }

        uint32_t sA = sbase + (uint32_t)(s % 3) * STAGE;
        uint32_t sB = sA + TILE_BYTES;
#pragma unroll
        for (int ks = 0; ks < 4; ks++) {
            uint32_t a[4][4], b[2][4];
#pragma unroll
            for (int mi = 0; mi < 4; mi++) {
                uint32_t addr = sA + (uint32_t)(wm * 64 + mi * 16 + lrow) * ROWB
                                   + (uint32_t)(ks * 32 + lkA * 2);
                ldm4(a[mi][0], a[mi][1], a[mi][2], a[mi][3], addr);
            }
#pragma unroll
            for (int g = 0; g < 2; g++) {
                uint32_t addr = sB + (uint32_t)(wn * 32 + g * 16 + nlB) * ROWB
                                   + (uint32_t)(ks * 32 + lkB * 2);
                ldm4(b[g][0], b[g][1], b[g][2], b[g][3], addr);
            }
#pragma unroll
            for (int mi = 0; mi < 4; mi++) {
#pragma unroll
                for (int g = 0; g < 2; g++) {
                    mma16816(acc[mi][g * 2],     a[mi], &b[g][0]);
                    mma16816(acc[mi][g * 2 + 1], a[mi], &b[g][2]);
                }
            }
        }
    }

    // ---- epilogue: tanh + va-dot; qW/va straight from L2 ----------------------
#pragma unroll
    for (int mi = 0; mi < 4; mi++) {
        float sumA = 0.f, sumB = 0.f;
        int rloc = wm * 64 + mi * 16 + (lid >> 2);
        int bA = rloc & 31;             // m0 is a multiple of 128
        int bB = (rloc + 8) & 31;
        const float* qa = g_qW + bA * H_DIM + n0;
        const float* qb = g_qW + bB * H_DIM + n0;
#pragma unroll
        for (int j = 0; j < 4; j++) {
            int nl = wn * 32 + j * 8 + 2 * (lid & 3);
            float2 va2 = *(const float2*)(va_w + n0 + nl);
            float2 qa2 = *(const float2*)(qa + nl);
            float2 qb2 = *(const float2*)(qb + nl);
            sumA += va2.x * tanh_a(acc[mi][j][0] + qa2.x)
                  + va2.y * tanh_a(acc[mi][j][1] + qa2.y);
            sumB += va2.x * tanh_a(acc[mi][j][2] + qb2.x)
                  + va2.y * tanh_a(acc[mi][j][3] + qb2.y);
        }
        sumA += __shfl_xor_sync(0xFFFFFFFFu, sumA, 1);
        sumA += __shfl_xor_sync(0xFFFFFFFFu, sumA, 2);
        sumB += __shfl_xor_sync(0xFFFFFFFFu, sumB, 1);
        sumB += __shfl_xor_sync(0xFFFFFFFFu, sumB, 2);
        if ((lid & 3) == 0) {
            int r = m0 + rloc;
            size_t slot = (size_t)(nt * 4 + wn) * M_TOTAL;
            g_partial[slot + r]     = sumA;
            g_partial[slot + r + 8] = sumB;
        }
    }
}

// ---------------- score reduce (full-chip) + softmax --------------------------
__global__ void score_reduce_kernel() {
    int r = blockIdx.x * 256 + threadIdx.x;   // 65536 threads, one per row
    float v = 0.0f;
#pragma unroll
    for (int p = 0; p < 32; p++) v += g_partial[(size_t)p * M_TOTAL + r];
    int b = r & 31, s = r >> 5;               // r = s*32 + b
    g_scores[b * S_DIM + s] = v;
}

__global__ void softmax_kernel(float* __restrict__ out) {
    int b = blockIdx.x, t = threadIdx.x;   // 256 threads
    __shared__ float sc[S_DIM];
    __shared__ float red[256];
    float lmax = -1e30f;
#pragma unroll
    for (int j = 0; j < 8; j++) {
        int s = t + j * 256;
        float v = g_scores[b * S_DIM + s];
        sc[s] = v;
        lmax = fmaxf(lmax, v);
    }
    red[t] = lmax; __syncthreads();
    for (int o = 128; o > 0; o >>= 1) {
        if (t < o) red[t] = fmaxf(red[t], red[t + o]);
        __syncthreads();
    }
    float mx = red[0];
    __syncthreads();
    float lsum = 0.0f;
#pragma unroll
    for (int j = 0; j < 8; j++) {
        int s = t + j * 256;
        float e = __expf(sc[s] - mx);
        sc[s] = e;
        lsum += e;
    }
    red[t] = lsum; __syncthreads();
    for (int o = 128; o > 0; o >>= 1) {
        if (t < o) red[t] += red[t + o];
        __syncthreads();
    }
    float inv = 1.0f / red[0];
#pragma unroll
    for (int j = 0; j < 8; j++) {
        int s = t + j * 256;
        out[B_DIM * H_DIM + b * S_DIM + s] = sc[s] * inv;
    }
}

__global__ void context_part_kernel(const float* __restrict__ out) {
    int b = blockIdx.x, chunk = blockIdx.y, t = threadIdx.x;   // 256 threads
    __shared__ float w_s[256];
    w_s[t] = out[B_DIM * H_DIM + b * S_DIM + chunk * 256 + t];
    __syncthreads();
    int h0 = t * 4;
    float a0 = 0.f, a1 = 0.f, a2 = 0.f, a3 = 0.f;
#pragma unroll 4
    for (int si = 0; si < 256; si++) {
        int s = chunk * 256 + si;
        const __half* kp = g_keyh + (((size_t)s * 32 + b) << 10) + h0;
        uint2 raw = *(const uint2*)kp;
        __half2 p0 = *(__half2*)&raw.x, p1 = *(__half2*)&raw.y;
        float w = w_s[si];
        float2 f0 = __half22float2(p0), f1 = __half22float2(p1);
        a0 += w * f0.x; a1 += w * f0.y; a2 += w * f1.x; a3 += w * f1.y;
    }
    float* cp = g_ctxpart + (((size_t)chunk * 32 + b) << 10) + h0;
    cp[0] = a0; cp[1] = a1; cp[2] = a2; cp[3] = a3;
}

__global__ void context_reduce_kernel(float* __restrict__ out) {
    int b = blockIdx.x, h = threadIdx.x;   // 1024 threads
    float acc = 0.0f;
#pragma unroll
    for (int c = 0; c < 8; c++)
        acc += g_ctxpart[(((size_t)c * 32 + b) << 10) + h];
    out[b * H_DIM + h] = acc;
}

// ---------------- launch ------------------------------------------------------
extern "C" void kernel_launch(void* const* d_in, const int* in_sizes, int n_in,
                              void* d_out, int out_size) {
    const float* query = (const float*)d_in[0];
    const float* key   = (const float*)d_in[1];
    const float* Wa_w  = (const float*)d_in[2];
    const float* Wa_b  = (const float*)d_in[3];
    const float* Ua_w  = (const float*)d_in[4];
    const float* Ua_b  = (const float*)d_in[5];
    const float* va_w  = (const float*)d_in[6];
    // d_in[7] (va_b) is a uniform score shift -> softmax-invariant -> unused
    float* out = (float*)d_out;

    cudaFuncSetAttribute(gemm_score_kernel,
                         cudaFuncAttributeMaxDynamicSharedMemorySize, GEMM_SMEM);

    prep_kernel<<<PREP_BLKS, 256>>>(key, Ua_w, query, Wa_w);
    qw_reduce_kernel<<<B_DIM, 1024>>>(Wa_b, Ua_b);
    gemm_score_kernel<<<dim3(8, 512), 256, GEMM_SMEM>>>(va_w);
    score_reduce_kernel<<<256, 256>>>();
    softmax_kernel<<<B_DIM, 256>>>(out);
    context_part_kernel<<<dim3(B_DIM, 8), 256>>>(out);
    context_reduce_kernel<<<B_DIM, 1024>>>(out);
}

// round 15
// speedup vs baseline: 1.2217x; 1.0658x over previous
#include <cuda_runtime.h>
#include <cuda_fp16.h>
#include <cstdint>

#define S_DIM 2048
#define B_DIM 32
#define H_DIM 1024
#define M_TOTAL (S_DIM * B_DIM)   // 65536 rows of the big GEMM

// ---------------- scratch (device globals; no allocations allowed) ----------
__device__ __align__(16) __half g_keyh[(size_t)M_TOTAL * H_DIM];   // 128 MB fp16 key
__device__ __align__(16) __half g_UaT[(size_t)H_DIM * H_DIM];      // Ua^T fp16 ([n][k], k contiguous)
__device__ __align__(16) float  g_qW[B_DIM * H_DIM];               // q@Wa + Wa_b + Ua_b
__device__ __align__(16) float  g_qWpart[8 * B_DIM * H_DIM];       // split-k partials
__device__ __align__(16) float  g_partial[(size_t)32 * M_TOTAL];   // per (N-tile x warp-col) score partials
__device__ __align__(16) float  g_scores[B_DIM * S_DIM];           // reduced scores, b-major
__device__ __align__(16) float  g_ctxpart[(size_t)8 * B_DIM * H_DIM];

// ---------------- small helpers ---------------------------------------------
__device__ __forceinline__ uint32_t smem_u32(const void* p) {
    uint32_t a;
    asm("{ .reg .u64 t; cvta.to.shared.u64 t, %1; cvt.u32.u64 %0, t; }" : "=r"(a) : "l"(p));
    return a;
}

__device__ __forceinline__ void cp16(uint32_t dst, const void* src) {
    asm volatile("cp.async.cg.shared.global [%0], [%1], 16;" :: "r"(dst), "l"(src));
}

__device__ __forceinline__ void ldm4(uint32_t& r0, uint32_t& r1, uint32_t& r2, uint32_t& r3,
                                     uint32_t addr) {
    asm volatile("ldmatrix.sync.aligned.m8n8.x4.shared.b16 {%0,%1,%2,%3}, [%4];"
                 : "=r"(r0), "=r"(r1), "=r"(r2), "=r"(r3) : "r"(addr));
}

__device__ __forceinline__ void mma16816(float* c, const uint32_t* a, const uint32_t* b) {
    asm volatile(
        "mma.sync.aligned.m16n8k16.row.col.f32.f16.f16.f32 "
        "{%0,%1,%2,%3}, {%4,%5,%6,%7}, {%8,%9}, {%0,%1,%2,%3};"
        : "+f"(c[0]), "+f"(c[1]), "+f"(c[2]), "+f"(c[3])
        : "r"(a[0]), "r"(a[1]), "r"(a[2]), "r"(a[3]), "r"(b[0]), "r"(b[1]));
}

__device__ __forceinline__ float tanh_a(float x) {
    float y;
    asm("tanh.approx.f32 %0, %1;" : "=f"(y) : "f"(x));
    return y;
}

__device__ __forceinline__ void mbar_init(uint32_t addr, uint32_t cnt) {
    asm volatile("mbarrier.init.shared.b64 [%0], %1;" :: "r"(addr), "r"(cnt) : "memory");
}
__device__ __forceinline__ void mbar_arrive(uint32_t addr) {
    asm volatile("mbarrier.arrive.shared.b64 _, [%0];" :: "r"(addr) : "memory");
}
__device__ __forceinline__ void cpasync_arrive(uint32_t addr) {
    asm volatile("cp.async.mbarrier.arrive.noinc.shared.b64 [%0];" :: "r"(addr) : "memory");
}
__device__ __forceinline__ void mbar_wait(uint32_t addr, int parity) {
    asm volatile(
        "{\n\t.reg .pred P;\n\t"
        "W_%=:\n\t"
        "mbarrier.try_wait.parity.acquire.cta.shared::cta.b64 P, [%0], %1, 0x989680;\n\t"
        "@P bra.uni D_%=;\n\t"
        "bra.uni W_%=;\n\t"
        "D_%=:\n\t}" :: "r"(addr), "r"(parity) : "memory");
}

// ---------------- fused prep kernel ------------------------------------------
#define PREP_QW_BLKS   256
#define PREP_TR_BLKS   1024
#define PREP_CV_BLKS   4096
#define PREP_BLKS      (PREP_QW_BLKS + PREP_TR_BLKS + PREP_CV_BLKS)

__global__ __launch_bounds__(256) void prep_kernel(
    const float* __restrict__ key, const float* __restrict__ Ua,
    const float* __restrict__ q,   const float* __restrict__ Wa) {
    __shared__ float smem[32 * 33];
    const int bid = blockIdx.x;
    const int t = threadIdx.x;

    if (bid < PREP_QW_BLKS) {
        int b = bid & 31, kc = bid >> 5;
        float* qs = smem;
        if (t < 128) qs[t] = q[b * H_DIM + kc * 128 + t];
        __syncthreads();
        float a0 = 0.f, a1 = 0.f, a2 = 0.f, a3 = 0.f;
#pragma unroll 4
        for (int c = 0; c < 128; c++) {
            float qc = qs[c];
            const float* row = Wa + ((size_t)(kc * 128 + c) << 10);
            a0 += qc * row[t];
            a1 += qc * row[t + 256];
            a2 += qc * row[t + 512];
            a3 += qc * row[t + 768];
        }
        float* o = g_qWpart + (((size_t)kc * 32 + b) << 10);
        o[t] = a0; o[t + 256] = a1; o[t + 512] = a2; o[t + 768] = a3;
    } else if (bid < PREP_QW_BLKS + PREP_TR_BLKS) {
        int b2 = bid - PREP_QW_BLKS;
        int bx = b2 & 31, by = b2 >> 5;
        int tx = t & 31, ty = t >> 5;        // 32 x 8
        float (*tile)[33] = (float (*)[33])smem;
        int x = bx * 32 + tx;
        int y = by * 32 + ty;
#pragma unroll
        for (int i = 0; i < 32; i += 8)
            tile[ty + i][tx] = Ua[(size_t)(y + i) * H_DIM + x];
        __syncthreads();
        int x2 = by * 32 + tx;
        int y2 = bx * 32 + ty;
#pragma unroll
        for (int i = 0; i < 32; i += 8)
            g_UaT[(size_t)(y2 + i) * H_DIM + x2] = __float2half_rn(tile[tx][ty + i]);
    } else {
        int b3 = bid - PREP_QW_BLKS - PREP_TR_BLKS;
        const float4* in4 = (const float4*)key;
        uint4* out4 = (uint4*)g_keyh;
        size_t n8 = (size_t)M_TOTAL * H_DIM / 8;
        for (size_t i = (size_t)b3 * 256 + t; i < n8; i += (size_t)PREP_CV_BLKS * 256) {
            float4 a = in4[2 * i], b = in4[2 * i + 1];
            uint4 o; __half2 h;
            h = __floats2half2_rn(a.x, a.y); o.x = *(uint32_t*)&h;
            h = __floats2half2_rn(a.z, a.w); o.y = *(uint32_t*)&h;
            h = __floats2half2_rn(b.x, b.y); o.z = *(uint32_t*)&h;
            h = __floats2half2_rn(b.z, b.w); o.w = *(uint32_t*)&h;
            out4[i] = o;
        }
    }
}

__global__ void qw_reduce_kernel(const float* __restrict__ Wb, const float* __restrict__ Ub) {
    int b = blockIdx.x, h = threadIdx.x;   // 1024 threads
    float acc = Wb[h] + Ub[h];
#pragma unroll
    for (int kc = 0; kc < 8; kc++)
        acc += g_qWpart[(((size_t)kc * 32 + b) << 10) + h];
    g_qW[b * H_DIM + h] = acc;
}

// ---------------- fused GEMM (mma.sync HMMA) + tanh + va-dot -----------------
// CTA tile 128(M) x 128(N), K chunks of 64, 3-stage pipeline with mbarrier
// full/empty handshake (no per-stage __syncthreads -> no warp convoy).
// 8 warps in 2(M) x 4(N); warp tile 64 x 32.
#define ROWB 144                       // smem bytes per 64-half row (128 + 16 pad)
#define TILE_BYTES (128 * ROWB)        // 18432 per operand tile
#define STAGE (2 * TILE_BYTES)         // 36864 (A tile + B tile)
#define SM_MBAR (3 * STAGE)            // full[3] then empty[3], 8B each
#define GEMM_SMEM (SM_MBAR + 64)       // 110656 -> 2 CTAs/SM

__global__ __launch_bounds__(256, 2) void gemm_score_kernel(const float* __restrict__ va_w) {
    extern __shared__ char sm[];
    uint32_t sbase = smem_u32(sm);
    const uint32_t mb_full  = sbase + SM_MBAR;        // + i*8
    const uint32_t mb_empty = sbase + SM_MBAR + 24;   // + i*8

    const int t = threadIdx.x;
    const int wid = t >> 5, lid = t & 31;
    const int nt = blockIdx.x;            // N-fastest for L2 reuse of A
    const int n0 = nt * 128;
    const int m0 = blockIdx.y * 128;
    const int wm = wid >> 2;              // 0..1
    const int wn = wid & 3;               // 0..3

    if (t == 0) {
#pragma unroll
        for (int i = 0; i < 3; i++) {
            mbar_init(mb_full + i * 8, 256);
            mbar_init(mb_empty + i * 8, 256);
        }
    }
    __syncthreads();   // mbarriers visible before any arrival

    auto load_stage = [&](int s, int buf) {
        uint32_t dA = sbase + (uint32_t)buf * STAGE;
#pragma unroll
        for (int i = 0; i < 4; i++) {
            int chunk = t + i * 256;            // 1024 chunks of 16B per operand
            int row = chunk >> 3, c = chunk & 7;
            uint32_t d = dA + (uint32_t)row * ROWB + (uint32_t)c * 16;
            cp16(d,              g_keyh + ((size_t)(m0 + row) << 10) + s * 64 + c * 8);
            cp16(d + TILE_BYTES, g_UaT  + ((size_t)(n0 + row) << 10) + s * 64 + c * 8);
        }
    };

    float acc[4][4][4];
#pragma unroll
    for (int i = 0; i < 4; i++)
#pragma unroll
        for (int j = 0; j < 4; j++)
#pragma unroll
            for (int k = 0; k < 4; k++) acc[i][j][k] = 0.0f;

    // prologue: fill stages 0 and 1
    load_stage(0, 0);
    cpasync_arrive(mb_full + 0 * 8);
    load_stage(1, 1);
    cpasync_arrive(mb_full + 1 * 8);

    const int lrow = lid & 15;
    const int lkA  = (lid >> 4) << 3;               // A: k half-offset 0/8
    const int nlB  = (lid & 7) + ((lid >> 4) << 3); // B: n row within 16-group
    const int lkB  = ((lid >> 3) & 1) << 3;         // B: k half-offset 0/8

    int cfs = 0, cfp = 0;     // consumer cursor over full[]
    int pes = 2, pep = 1;     // producer cursor over empty[] (first wait passes)

    for (int s = 0; s < 16; s++) {
        mbar_wait(mb_full + cfs * 8, cfp);    // data for stage s landed

        if (s < 14) {                         // refill the buffer stage s-1 used
            mbar_wait(mb_empty + pes * 8, pep);
            load_stage(s + 2, pes);
            cpasync_arrive(mb_full + pes * 8);
            if (++pes == 3) { pes = 0; pep ^= 1; }
        }

        uint32_t sA = sbase + (uint32_t)cfs * STAGE;
        uint32_t sB = sA + TILE_BYTES;
#pragma unroll
        for (int kk = 0; kk < 4; kk++) {
            int ks = (kk + wid) & 3;          // warp-rotated k order (de-phase LSU)
            uint32_t a[4][4], b[2][4];
#pragma unroll
            for (int mi = 0; mi < 4; mi++) {
                uint32_t addr = sA + (uint32_t)(wm * 64 + mi * 16 + lrow) * ROWB
                                   + (uint32_t)(ks * 32 + lkA * 2);
                ldm4(a[mi][0], a[mi][1], a[mi][2], a[mi][3], addr);
            }
#pragma unroll
            for (int g = 0; g < 2; g++) {
                uint32_t addr = sB + (uint32_t)(wn * 32 + g * 16 + nlB) * ROWB
                                   + (uint32_t)(ks * 32 + lkB * 2);
                ldm4(b[g][0], b[g][1], b[g][2], b[g][3], addr);
            }
#pragma unroll
            for (int mi = 0; mi < 4; mi++) {
#pragma unroll
                for (int g = 0; g < 2; g++) {
                    mma16816(acc[mi][g * 2],     a[mi], &b[g][0]);
                    mma16816(acc[mi][g * 2 + 1], a[mi], &b[g][2]);
                }
            }
        }

        mbar_arrive(mb_empty + cfs * 8);      // this thread done reading buffer
        if (++cfs == 3) { cfs = 0; cfp ^= 1; }
    }

    // ---- epilogue: tanh + va-dot; qW/va straight from L2 ----------------------
#pragma unroll
    for (int mi = 0; mi < 4; mi++) {
        float sumA = 0.f, sumB = 0.f;
        int rloc = wm * 64 + mi * 16 + (lid >> 2);
        int bA = rloc & 31;             // m0 is a multiple of 128
        int bB = (rloc + 8) & 31;
        const float* qa = g_qW + bA * H_DIM + n0;
        const float* qb = g_qW + bB * H_DIM + n0;
#pragma unroll
        for (int j = 0; j < 4; j++) {
            int nl = wn * 32 + j * 8 + 2 * (lid & 3);
            float2 va2 = *(const float2*)(va_w + n0 + nl);
            float2 qa2 = *(const float2*)(qa + nl);
            float2 qb2 = *(const float2*)(qb + nl);
            sumA += va2.x * tanh_a(acc[mi][j][0] + qa2.x)
                  + va2.y * tanh_a(acc[mi][j][1] + qa2.y);
            sumB += va2.x * tanh_a(acc[mi][j][2] + qb2.x)
                  + va2.y * tanh_a(acc[mi][j][3] + qb2.y);
        }
        sumA += __shfl_xor_sync(0xFFFFFFFFu, sumA, 1);
        sumA += __shfl_xor_sync(0xFFFFFFFFu, sumA, 2);
        sumB += __shfl_xor_sync(0xFFFFFFFFu, sumB, 1);
        sumB += __shfl_xor_sync(0xFFFFFFFFu, sumB, 2);
        if ((lid & 3) == 0) {
            int r = m0 + rloc;
            size_t slot = (size_t)(nt * 4 + wn) * M_TOTAL;
            g_partial[slot + r]     = sumA;
            g_partial[slot + r + 8] = sumB;
        }
    }
}

// ---------------- score reduce (full-chip) + softmax --------------------------
__global__ void score_reduce_kernel() {
    int r = blockIdx.x * 256 + threadIdx.x;   // 65536 threads, one per row
    float v = 0.0f;
#pragma unroll
    for (int p = 0; p < 32; p++) v += g_partial[(size_t)p * M_TOTAL + r];
    int b = r & 31, s = r >> 5;               // r = s*32 + b
    g_scores[b * S_DIM + s] = v;
}

__global__ void softmax_kernel(float* __restrict__ out) {
    int b = blockIdx.x, t = threadIdx.x;   // 256 threads
    __shared__ float sc[S_DIM];
    __shared__ float red[256];
    float lmax = -1e30f;
#pragma unroll
    for (int j = 0; j < 8; j++) {
        int s = t + j * 256;
        float v = g_scores[b * S_DIM + s];
        sc[s] = v;
        lmax = fmaxf(lmax, v);
    }
    red[t] = lmax; __syncthreads();
    for (int o = 128; o > 0; o >>= 1) {
        if (t < o) red[t] = fmaxf(red[t], red[t + o]);
        __syncthreads();
    }
    float mx = red[0];
    __syncthreads();
    float lsum = 0.0f;
#pragma unroll
    for (int j = 0; j < 8; j++) {
        int s = t + j * 256;
        float e = __expf(sc[s] - mx);
        sc[s] = e;
        lsum += e;
    }
    red[t] = lsum; __syncthreads();
    for (int o = 128; o > 0; o >>= 1) {
        if (t < o) red[t] += red[t + o];
        __syncthreads();
    }
    float inv = 1.0f / red[0];
#pragma unroll
    for (int j = 0; j < 8; j++) {
        int s = t + j * 256;
        out[B_DIM * H_DIM + b * S_DIM + s] = sc[s] * inv;
    }
}

__global__ void context_part_kernel(const float* __restrict__ out) {
    int b = blockIdx.x, chunk = blockIdx.y, t = threadIdx.x;   // 256 threads
    __shared__ float w_s[256];
    w_s[t] = out[B_DIM * H_DIM + b * S_DIM + chunk * 256 + t];
    __syncthreads();
    int h0 = t * 4;
    float a0 = 0.f, a1 = 0.f, a2 = 0.f, a3 = 0.f;
#pragma unroll 4
    for (int si = 0; si < 256; si++) {
        int s = chunk * 256 + si;
        const __half* kp = g_keyh + (((size_t)s * 32 + b) << 10) + h0;
        uint2 raw = *(const uint2*)kp;
        __half2 p0 = *(__half2*)&raw.x, p1 = *(__half2*)&raw.y;
        float w = w_s[si];
        float2 f0 = __half22float2(p0), f1 = __half22float2(p1);
        a0 += w * f0.x; a1 += w * f0.y; a2 += w * f1.x; a3 += w * f1.y;
    }
    float* cp = g_ctxpart + (((size_t)chunk * 32 + b) << 10) + h0;
    cp[0] = a0; cp[1] = a1; cp[2] = a2; cp[3] = a3;
}

__global__ void context_reduce_kernel(float* __restrict__ out) {
    int b = blockIdx.x, h = threadIdx.x;   // 1024 threads
    float acc = 0.0f;
#pragma unroll
    for (int c = 0; c < 8; c++)
        acc += g_ctxpart[(((size_t)c * 32 + b) << 10) + h];
    out[b * H_DIM + h] = acc;
}

// ---------------- launch ------------------------------------------------------
extern "C" void kernel_launch(void* const* d_in, const int* in_sizes, int n_in,
                              void* d_out, int out_size) {
    const float* query = (const float*)d_in[0];
    const float* key   = (const float*)d_in[1];
    const float* Wa_w  = (const float*)d_in[2];
    const float* Wa_b  = (const float*)d_in[3];
    const float* Ua_w  = (const float*)d_in[4];
    const float* Ua_b  = (const float*)d_in[5];
    const float* va_w  = (const float*)d_in[6];
    // d_in[7] (va_b) is a uniform score shift -> softmax-invariant -> unused
    float* out = (float*)d_out;

    cudaFuncSetAttribute(gemm_score_kernel,
                         cudaFuncAttributeMaxDynamicSharedMemorySize, GEMM_SMEM);

    prep_kernel<<<PREP_BLKS, 256>>>(key, Ua_w, query, Wa_w);
    qw_reduce_kernel<<<B_DIM, 1024>>>(Wa_b, Ua_b);
    gemm_score_kernel<<<dim3(8, 512), 256, GEMM_SMEM>>>(va_w);
    score_reduce_kernel<<<256, 256>>>();
    softmax_kernel<<<B_DIM, 256>>>(out);
    context_part_kernel<<<dim3(B_DIM, 8), 256>>>(out);
    context_reduce_kernel<<<B_DIM, 1024>>>(out);
}